// round 1
// baseline (speedup 1.0000x reference)
#include <cuda_runtime.h>
#include <math.h>

// Problem constants
#define NTOK 32768      // B*F*S tokens (raw reshape)
#define SLEN 1024
#define DMOD 512
#define DFF  2048
#define NBH  256        // BF * H
#define HDK  64

// Scratch (device globals; no allocation allowed)
__device__ float g_q[NBH * SLEN * HDK];
__device__ float g_k[NBH * SLEN * HDK];
__device__ float g_v[NBH * SLEN * HDK];
__device__ float g_ctx[NTOK * DMOD];
__device__ float g_t1[NTOK * DMOD];
__device__ float g_h[NTOK * DMOD];
__device__ float g_ff[NTOK * DFF];

// ---------------------------------------------------------------------------
// Generic fp32 SGEMM (NT): C[m,n] = sum_k A[m,k] * W[n,k] + bias[n]
// 128x128 tile, BK=8, 256 threads, 8x8 per-thread microtile.
// MODE 0: plain store   MODE 1: exact GELU   MODE 2: QKV (z selects W/b/C,
//         scatter into [bf][h][s][dk])
// ---------------------------------------------------------------------------
template<int MODE>
__global__ __launch_bounds__(256) void sgemm_kernel(
    const float* __restrict__ A, int K, int N,
    const float* __restrict__ W0, const float* __restrict__ bia0, float* __restrict__ C0,
    const float* __restrict__ W1, const float* __restrict__ bia1, float* __restrict__ C1,
    const float* __restrict__ W2, const float* __restrict__ bia2, float* __restrict__ C2)
{
    const float* W = W0; const float* bias = bia0; float* C = C0;
    if (MODE == 2) {
        if (blockIdx.z == 1)      { W = W1; bias = bia1; C = C1; }
        else if (blockIdx.z == 2) { W = W2; bias = bia2; C = C2; }
    }

    __shared__ float As[8][128];
    __shared__ float Bs[8][128];

    const int tid = threadIdx.x;
    const int bm = blockIdx.y << 7;
    const int bn = blockIdx.x << 7;
    const int lr = tid >> 1;            // 0..127
    const int lc = (tid & 1) << 2;      // 0 or 4
    const float* Ap = A + (size_t)(bm + lr) * K + lc;
    const float* Wp = W + (size_t)(bn + lr) * K + lc;
    const int ty = tid >> 4;            // 0..15
    const int tx = tid & 15;            // 0..15

    float acc[8][8];
#pragma unroll
    for (int i = 0; i < 8; ++i)
#pragma unroll
        for (int j = 0; j < 8; ++j) acc[i][j] = 0.f;

    for (int k0 = 0; k0 < K; k0 += 8) {
        float4 a4 = *(const float4*)(Ap + k0);
        float4 w4 = *(const float4*)(Wp + k0);
        As[lc + 0][lr] = a4.x; As[lc + 1][lr] = a4.y;
        As[lc + 2][lr] = a4.z; As[lc + 3][lr] = a4.w;
        Bs[lc + 0][lr] = w4.x; Bs[lc + 1][lr] = w4.y;
        Bs[lc + 2][lr] = w4.z; Bs[lc + 3][lr] = w4.w;
        __syncthreads();
#pragma unroll
        for (int kk = 0; kk < 8; ++kk) {
            float a[8], b[8];
            *(float4*)&a[0] = *(const float4*)&As[kk][ty << 3];
            *(float4*)&a[4] = *(const float4*)&As[kk][(ty << 3) + 4];
            *(float4*)&b[0] = *(const float4*)&Bs[kk][tx << 3];
            *(float4*)&b[4] = *(const float4*)&Bs[kk][(tx << 3) + 4];
#pragma unroll
            for (int i = 0; i < 8; ++i)
#pragma unroll
                for (int j = 0; j < 8; ++j)
                    acc[i][j] += a[i] * b[j];
        }
        __syncthreads();
    }

#pragma unroll
    for (int i = 0; i < 8; ++i) {
        const int row = bm + (ty << 3) + i;
#pragma unroll
        for (int j = 0; j < 8; ++j) {
            const int col = bn + (tx << 3) + j;
            float v = acc[i][j] + bias[col];
            if (MODE == 1)
                v = 0.5f * v * (1.0f + erff(v * 0.70710678118654752f));
            if (MODE == 2) {
                // row = t = bf*1024 + s ; col = h*64 + dk ; dst [bf][h][s][dk]
                const int idx = (((row >> 10) << 3) + (col >> 6)) * (SLEN * HDK)
                              + ((row & 1023) << 6) + (col & 63);
                C[idx] = v;
            } else {
                C[(size_t)row * N + col] = v;
            }
        }
    }
}

// ---------------------------------------------------------------------------
// Flash attention, fp32. grid = (S/64, BF*H), block = 64.
// One query row per thread (Q and O fully in registers).
// Key-boost & scale & log2(e) folded into the K tile at load time.
// Exactly one exp2 per (query,key) via per-tile deferred max.
// ---------------------------------------------------------------------------
__global__ __launch_bounds__(64) void attn_kernel(const unsigned int* __restrict__ mask)
{
    __shared__ float Ks[64 * 64];
    __shared__ float Vs[64 * 64];
    __shared__ float Ss[64 * 64];   // per-thread score row, bank-swizzled

    const int tid = threadIdx.x;
    const int bh  = blockIdx.y;     // bf*8 + h
    const int bf  = bh >> 3;
    const int bb  = bf >> 3;        // batch row of eclipse_mask (F=8)
    const int q0  = blockIdx.x << 6;
    const float LOG2E = 1.4426950408889634f;

    const float* Qp = g_q + ((size_t)bh << 16) + ((size_t)(q0 + tid) << 6);
    float q[64];
#pragma unroll
    for (int i = 0; i < 16; ++i)
        *(float4*)&q[i * 4] = *(const float4*)(Qp + i * 4);

    float o[64];
#pragma unroll
    for (int i = 0; i < 64; ++i) o[i] = 0.f;
    float m = -1e30f, l = 0.f;

    for (int kt = 0; kt < 16; ++kt) {
        const int krow = (kt << 6) + tid;
        const float fac = (mask[bb * SLEN + krow] != 0u) ? (0.25f * LOG2E)
                                                         : (0.125f * LOG2E);
        const float4* Kr = (const float4*)(g_k + ((size_t)bh << 16) + ((size_t)krow << 6));
        const float4* Vr = (const float4*)(g_v + ((size_t)bh << 16) + ((size_t)krow << 6));
        float4* Kd = (float4*)&Ks[tid << 6];
        float4* Vd = (float4*)&Vs[tid << 6];
#pragma unroll
        for (int i = 0; i < 16; ++i) {
            float4 kv = Kr[i];
            kv.x *= fac; kv.y *= fac; kv.z *= fac; kv.w *= fac;
            Kd[i] = kv;
            Vd[i] = Vr[i];
        }
        __syncthreads();

        float tmax = -1e30f;
#pragma unroll 4
        for (int j = 0; j < 64; ++j) {
            const float* kr = &Ks[j << 6];
            float a0 = 0.f, a1 = 0.f, a2 = 0.f, a3 = 0.f;
#pragma unroll
            for (int kk = 0; kk < 64; kk += 4) {
                float4 kv = *(const float4*)(kr + kk);
                a0 += q[kk + 0] * kv.x; a1 += q[kk + 1] * kv.y;
                a2 += q[kk + 2] * kv.z; a3 += q[kk + 3] * kv.w;
            }
            float s = (a0 + a1) + (a2 + a3);            // already in log2-domain
            Ss[(tid << 6) + ((j + tid) & 63)] = s;      // swizzled, private row
            tmax = fmaxf(tmax, s);
        }

        const float mn = fmaxf(m, tmax);
        const float alpha = exp2f(m - mn);
        l *= alpha;
#pragma unroll
        for (int i = 0; i < 64; ++i) o[i] *= alpha;

#pragma unroll 2
        for (int j = 0; j < 64; ++j) {
            const float p = exp2f(Ss[(tid << 6) + ((j + tid) & 63)] - mn);
            l += p;
            const float* vr = &Vs[j << 6];
#pragma unroll
            for (int kk = 0; kk < 64; kk += 4) {
                float4 vv = *(const float4*)(vr + kk);
                o[kk + 0] += p * vv.x; o[kk + 1] += p * vv.y;
                o[kk + 2] += p * vv.z; o[kk + 3] += p * vv.w;
            }
        }
        m = mn;
        __syncthreads();
    }

    const float inv = 1.0f / l;
    const int t = bf * SLEN + q0 + tid;
    float* op = g_ctx + (size_t)t * DMOD + ((bh & 7) << 6);
#pragma unroll
    for (int i = 0; i < 16; ++i) {
        float4 v;
        v.x = o[i * 4 + 0] * inv; v.y = o[i * 4 + 1] * inv;
        v.z = o[i * 4 + 2] * inv; v.w = o[i * 4 + 3] * inv;
        *(float4*)(op + i * 4) = v;
    }
}

// ---------------------------------------------------------------------------
// Residual-add + LayerNorm. One warp per token (D=512 = 16 floats/lane).
// block = 256 (8 tokens/block), grid = NTOK/8.
// ---------------------------------------------------------------------------
__global__ __launch_bounds__(256) void ln_kernel(
    const float* __restrict__ X, const float* __restrict__ Y,
    const float* __restrict__ gam, const float* __restrict__ bet,
    float* __restrict__ out)
{
    const int lane = threadIdx.x & 31;
    const int t = (blockIdx.x << 3) + (threadIdx.x >> 5);
    const float4* xp = (const float4*)(X + (size_t)t * DMOD);
    const float4* yp = (const float4*)(Y + (size_t)t * DMOD);

    float4 r[4];
    float sum = 0.f, sq = 0.f;
#pragma unroll
    for (int i = 0; i < 4; ++i) {
        const int idx = lane + (i << 5);
        float4 a = xp[idx], b = yp[idx];
        float4 v = make_float4(a.x + b.x, a.y + b.y, a.z + b.z, a.w + b.w);
        r[i] = v;
        sum += (v.x + v.y) + (v.z + v.w);
        sq  += (v.x * v.x + v.y * v.y) + (v.z * v.z + v.w * v.w);
    }
#pragma unroll
    for (int off = 16; off; off >>= 1) {
        sum += __shfl_xor_sync(0xffffffffu, sum, off);
        sq  += __shfl_xor_sync(0xffffffffu, sq, off);
    }
    const float mean = sum * (1.0f / 512.0f);
    const float var  = sq * (1.0f / 512.0f) - mean * mean;
    const float rstd = rsqrtf(var + 1e-5f);

    float4* op = (float4*)(out + (size_t)t * DMOD);
    const float4* gp = (const float4*)gam;
    const float4* bp = (const float4*)bet;
#pragma unroll
    for (int i = 0; i < 4; ++i) {
        const int idx = lane + (i << 5);
        float4 g = gp[idx], be = bp[idx], v = r[i];
        float4 o4;
        o4.x = (v.x - mean) * rstd * g.x + be.x;
        o4.y = (v.y - mean) * rstd * g.y + be.y;
        o4.z = (v.z - mean) * rstd * g.z + be.z;
        o4.w = (v.w - mean) * rstd * g.w + be.w;
        op[idx] = o4;
    }
}

// ---------------------------------------------------------------------------
extern "C" void kernel_launch(void* const* d_in, const int* in_sizes, int n_in,
                              void* d_out, int out_size)
{
    const float* x   = (const float*)d_in[0];
    const unsigned int* mask = (const unsigned int*)d_in[1];
    const float* wq  = (const float*)d_in[2];
    const float* bq  = (const float*)d_in[3];
    const float* wk  = (const float*)d_in[4];
    const float* bk  = (const float*)d_in[5];
    const float* wv  = (const float*)d_in[6];
    const float* bv  = (const float*)d_in[7];
    const float* wo  = (const float*)d_in[8];
    const float* bo  = (const float*)d_in[9];
    const float* w1  = (const float*)d_in[10];
    const float* b1  = (const float*)d_in[11];
    const float* w2  = (const float*)d_in[12];
    const float* b2  = (const float*)d_in[13];
    const float* g1  = (const float*)d_in[14];
    const float* be1 = (const float*)d_in[15];
    const float* g2  = (const float*)d_in[16];
    const float* be2 = (const float*)d_in[17];
    float* out = (float*)d_out;

    float *q_p, *k_p, *v_p, *ctx_p, *t1_p, *h_p, *ff_p;
    cudaGetSymbolAddress((void**)&q_p,  g_q);
    cudaGetSymbolAddress((void**)&k_p,  g_k);
    cudaGetSymbolAddress((void**)&v_p,  g_v);
    cudaGetSymbolAddress((void**)&ctx_p, g_ctx);
    cudaGetSymbolAddress((void**)&t1_p, g_t1);
    cudaGetSymbolAddress((void**)&h_p,  g_h);
    cudaGetSymbolAddress((void**)&ff_p, g_ff);

    dim3 blk(256);

    // 1) QKV projections (one launch, z = 0/1/2), scattered to [bf][h][s][dk]
    sgemm_kernel<2><<<dim3(4, 256, 3), blk>>>(x, 512, 512,
        wq, bq, q_p, wk, bk, k_p, wv, bv, v_p);

    // 2) attention with eclipse boost -> g_ctx [t, h*64+dk]
    attn_kernel<<<dim3(16, 256), 64>>>(mask);

    // 3) output projection -> g_t1
    sgemm_kernel<0><<<dim3(4, 256, 1), blk>>>(ctx_p, 512, 512,
        wo, bo, t1_p, nullptr, nullptr, nullptr, nullptr, nullptr, nullptr);

    // 4) h = LN(x + attn_out)
    ln_kernel<<<NTOK / 8, 256>>>(x, t1_p, g1, be1, h_p);

    // 5) FFN up + exact GELU -> g_ff
    sgemm_kernel<1><<<dim3(16, 256, 1), blk>>>(h_p, 512, 2048,
        w1, b1, ff_p, nullptr, nullptr, nullptr, nullptr, nullptr, nullptr);

    // 6) FFN down -> g_t1
    sgemm_kernel<0><<<dim3(4, 256, 1), blk>>>(ff_p, 2048, 512,
        w2, b2, t1_p, nullptr, nullptr, nullptr, nullptr, nullptr, nullptr);

    // 7) out = LN(h + ffn_out)
    ln_kernel<<<NTOK / 8, 256>>>(h_p, t1_p, g2, be2, out);
}